// round 14
// baseline (speedup 1.0000x reference)
#include <cuda_runtime.h>
#include <cstdint>
#include <math.h>

#define T_STEPS 256
#define BATCH   64
#define HID     256
#define G3      768           // 3*HID
#define VOCAB   5000
#define NBLK    40            // ceil(5000/128)

typedef unsigned long long u64;

// Scratch (static __device__ arrays: allowed; no runtime allocation)
__device__ __align__(16) float g_MX[(size_t)T_STEPS * BATCH * G3];   // [t][b][3H]
__device__ __align__(16) float g_Y [(size_t)T_STEPS * BATCH * HID];  // [t][b][H]

// ---------------------------------------------------------------------------
// Kernel 1: MX[t][b][n] = kernel[tokens[b][t]][n] + b_in[n]   (gather)
// ---------------------------------------------------------------------------
__global__ void mx_kernel(const int* __restrict__ tokens,
                          const float* __restrict__ Wk,
                          const float* __restrict__ bias) {
    int idx = blockIdx.x * 256 + threadIdx.x;
    int n  = idx % G3;
    int tb = idx / G3;
    int b  = tb % BATCH;
    int t  = tb / BATCH;
    int tok = tokens[b * T_STEPS + t];
    g_MX[idx] = Wk[(size_t)tok * G3 + n] + bias[n];
}

// ---------------------------------------------------------------------------
// Common helpers
// ---------------------------------------------------------------------------
__device__ __forceinline__ uint32_t smem_u32(const void* p) {
    uint32_t a;
    asm("{ .reg .u64 t; cvta.to.shared.u64 t, %1; cvt.u32.u64 %0, t; }"
        : "=r"(a) : "l"(p));
    return a;
}
__device__ __forceinline__ void st_cluster_f32(uint32_t laddr, int rank, float v) {
    uint32_t ra;
    asm volatile("mapa.shared::cluster.u32 %0, %1, %2;" : "=r"(ra) : "r"(laddr), "r"(rank));
    asm volatile("st.shared::cluster.f32 [%0], %1;" :: "r"(ra), "f"(v) : "memory");
}
__device__ __forceinline__ u64 fma2(u64 a, u64 b, u64 c) {
    u64 d;
    asm("fma.rn.f32x2 %0, %1, %2, %3;" : "=l"(d) : "l"(a), "l"(b), "l"(c));
    return d;
}
__device__ __forceinline__ u64 packf2(float lo, float hi) {
    u64 d;
    asm("mov.b64 %0, {%1, %2};" : "=l"(d) : "f"(lo), "f"(hi));
    return d;
}
__device__ __forceinline__ float sumf2(u64 p) {
    return __uint_as_float((unsigned)p) + __uint_as_float((unsigned)(p >> 32));
}
__device__ __forceinline__ float lof2(u64 p) { return __uint_as_float((unsigned)p); }
__device__ __forceinline__ float hif2(u64 p) { return __uint_as_float((unsigned)(p >> 32)); }
__device__ __forceinline__ float sigmoidf_(float x) { return 1.0f / (1.0f + __expf(-x)); }

// ---------------------------------------------------------------------------
// Kernel 2: GRU scan (UNCHANGED from passing R8/R10/R13)
// ---------------------------------------------------------------------------
#define HPAD 288

__global__ void __cluster_dims__(8, 1, 1) __launch_bounds__(256, 1) scan_kernel(
    const float* __restrict__ h0,
    const float* __restrict__ rkernel,
    const float* __restrict__ bias,
    float* __restrict__ out, int write_hlast)
{
    __shared__ float hb[2][4][HPAD];
    const int tid = threadIdx.x;
    const int jj = tid >> 3;
    const int o  = tid & 7;
    uint32_t crank;
    asm("mov.u32 %0, %%cluster_ctarank;" : "=r"(crank));
    const int cid  = blockIdx.x >> 3;
    const int seq0 = cid * 4;
    const int c    = (int)crank * 32 + jj;
    const int kbase = o * 32;

    u64 w2[3][16];
    #pragma unroll
    for (int g = 0; g < 3; ++g)
        #pragma unroll
        for (int ii = 0; ii < 16; ++ii) {
            float a = rkernel[(size_t)(kbase + 2 * ii)     * G3 + g * HID + c];
            float b = rkernel[(size_t)(kbase + 2 * ii + 1) * G3 + g * HID + c];
            w2[g][ii] = packf2(a, b);
        }
    const float brz = bias[G3 + c];
    const float brr = bias[G3 + HID + c];
    const float brh = bias[G3 + 2 * HID + c];

    for (int e = tid; e < 4 * HID; e += 256) {
        int s = e >> 8, k = e & 255;
        hb[0][s][k + ((k >> 5) << 2)] = h0[(size_t)(seq0 + s) * HID + k];
    }
    const uint32_t hb_base = smem_u32(&hb[0][0][0]);
    const int padc = (int)crank * 36 + jj;
    __syncthreads();
    asm volatile("barrier.cluster.arrive.aligned;" ::: "memory");
    asm volatile("barrier.cluster.wait.aligned;"   ::: "memory");

    for (int t = 0; t < T_STEPS; ++t) {
        const int cur = t & 1, nxt = cur ^ 1;
        const float* mxp = g_MX + ((size_t)t * BATCH + seq0) * G3 + c;
        float mxz[4], mxr[4], mxh[4];
        #pragma unroll
        for (int s = 0; s < 4; ++s) {
            mxz[s] = mxp[(size_t)s * G3];
            mxr[s] = mxp[(size_t)s * G3 + HID];
            mxh[s] = mxp[(size_t)s * G3 + 2 * HID];
        }
        u64 acc[3][4];
        #pragma unroll
        for (int g = 0; g < 3; ++g)
            #pragma unroll
            for (int s = 0; s < 4; ++s) acc[g][s] = 0ull;
        #pragma unroll
        for (int s = 0; s < 4; ++s) {
            const float* hrow = &hb[cur][s][o * 36];
            #pragma unroll
            for (int q = 0; q < 8; ++q) {
                ulonglong2 hp = *reinterpret_cast<const ulonglong2*>(hrow + q * 4);
                #pragma unroll
                for (int g = 0; g < 3; ++g) {
                    acc[g][s] = fma2(w2[g][2 * q],     hp.x, acc[g][s]);
                    acc[g][s] = fma2(w2[g][2 * q + 1], hp.y, acc[g][s]);
                }
            }
        }
        float red[12];
        #pragma unroll
        for (int g = 0; g < 3; ++g)
            #pragma unroll
            for (int s = 0; s < 4; ++s) red[g * 4 + s] = sumf2(acc[g][s]);
        #pragma unroll
        for (int m = 1; m <= 4; m <<= 1)
            #pragma unroll
            for (int v = 0; v < 12; ++v)
                red[v] += __shfl_xor_sync(0xFFFFFFFFu, red[v], m);

        float hn[4];
        #pragma unroll
        for (int s = 0; s < 4; ++s) {
            float az = red[s], ar = red[4 + s], ah = red[8 + s];
            float z = sigmoidf_(mxz[s] + az + brz);
            float r = sigmoidf_(mxr[s] + ar + brr);
            float cand = tanhf(mxh[s] + r * (ah + brh));
            float hp0 = hb[cur][s][padc];
            hn[s] = z * hp0 + (1.0f - z) * cand;
        }
        #pragma unroll
        for (int s = 0; s < 4; ++s) {
            uint32_t la = hb_base + (uint32_t)(((nxt * 4 + s) * HPAD + padc) * 4);
            st_cluster_f32(la, o, hn[s]);
        }
        asm volatile("barrier.cluster.arrive.aligned;" ::: "memory");
        if (o == 0) {
            #pragma unroll
            for (int s = 0; s < 4; ++s)
                g_Y[((size_t)t * BATCH + seq0 + s) * HID + c] = hn[s];
            if (write_hlast && t == T_STEPS - 1) {
                size_t hl = (size_t)VOCAB * (T_STEPS * BATCH);
                #pragma unroll
                for (int s = 0; s < 4; ++s)
                    out[hl + (size_t)(seq0 + s) * HID + c] = hn[s];
            }
        }
        asm volatile("barrier.cluster.wait.aligned;" ::: "memory");
    }
}

// ---------------------------------------------------------------------------
// Kernel 3: out = Y[16384,256] @ Wd[256,5000] + bd — pure-fp32 f32x2 SIMT GEMM.
// FMA pipe (rt2/SMSP, 2 MAC/lane) = 128 MAC/cyc/SM, ~2x the sm_103 mma.sync
// tf32 fallback rate, with exact fp32 math.
// 128x128 tile/CTA, 256 threads as 16(ty,m) x 16(tx,n); thread = 8m x 8n.
// A staged transposed [k][m] (reads broadcast); B staged [k][n] with 32-float
// skew so the tx*8 read pattern is bank-conflict-free LDS.128.
// ---------------------------------------------------------------------------
#define ASTR 132                 // A row stride (floats)
#define BSTR 144                 // B row stride (floats); 128 data + 12 skew + pad
#define BSKEW(n) ((n) + (((n) >> 5) << 2))

__global__ void __launch_bounds__(256) proj_kernel(
    const float* __restrict__ Wd, const float* __restrict__ bd,
    float* __restrict__ out)
{
    __shared__ __align__(16) float Asm[32 * ASTR];   // [k][m]
    __shared__ __align__(16) float Bsm[32 * BSTR];   // [k][skewed n]
    const int tid = threadIdx.x;
    const int ty = tid >> 4, tx = tid & 15;
    const int n0 = blockIdx.x * 128;
    const int i0 = blockIdx.y * 128;

    u64 acc[8][4];
    #pragma unroll
    for (int m = 0; m < 8; ++m)
        #pragma unroll
        for (int p = 0; p < 4; ++p) acc[m][p] = 0ull;

    const float* arow = &Asm[ty * 8];
    const float* brow = &Bsm[BSKEW(tx * 8)];

    for (int ch = 0; ch < 8; ++ch) {
        const int k0 = ch * 32;
        // ---- A fill: g_Y[i0+m][k0+k4..+3] -> Asm[k][m] (transpose) ----
        #pragma unroll
        for (int it = 0; it < 4; ++it) {
            int g = tid + it * 256;            // 0..1023
            int m = g >> 3;
            int k4 = (g & 7) << 2;
            float4 v = *reinterpret_cast<const float4*>(
                &g_Y[(size_t)(i0 + m) * HID + k0 + k4]);
            Asm[(k4 + 0) * ASTR + m] = v.x;
            Asm[(k4 + 1) * ASTR + m] = v.y;
            Asm[(k4 + 2) * ASTR + m] = v.z;
            Asm[(k4 + 3) * ASTR + m] = v.w;
        }
        // ---- B fill: Wd[k0+k][n0+c4..+3] -> Bsm[k][skew(c4)] ----
        #pragma unroll
        for (int it = 0; it < 4; ++it) {
            int g = tid + it * 256;            // 0..1023
            int k = g >> 5;
            int c4 = (g & 31) << 2;
            int col = n0 + c4;
            float4 v = make_float4(0.f, 0.f, 0.f, 0.f);
            if (col < VOCAB)
                v = *reinterpret_cast<const float4*>(
                    &Wd[(size_t)(k0 + k) * VOCAB + col]);
            *reinterpret_cast<float4*>(&Bsm[k * BSTR + BSKEW(c4)]) = v;
        }
        __syncthreads();

        // ---- mainloop: 32 k-iters, 32 fma2 each ----
        #pragma unroll 8
        for (int k = 0; k < 32; ++k) {
            float4 a01 = *reinterpret_cast<const float4*>(arow + k * ASTR);
            float4 a23 = *reinterpret_cast<const float4*>(arow + k * ASTR + 4);
            ulonglong2 bv0 = *reinterpret_cast<const ulonglong2*>(brow + k * BSTR);
            ulonglong2 bv1 = *reinterpret_cast<const ulonglong2*>(brow + k * BSTR + 4);
            float am[8] = {a01.x, a01.y, a01.z, a01.w, a23.x, a23.y, a23.z, a23.w};
            #pragma unroll
            for (int m = 0; m < 8; ++m) {
                u64 a2 = packf2(am[m], am[m]);
                acc[m][0] = fma2(a2, bv0.x, acc[m][0]);
                acc[m][1] = fma2(a2, bv0.y, acc[m][1]);
                acc[m][2] = fma2(a2, bv1.x, acc[m][2]);
                acc[m][3] = fma2(a2, bv1.y, acc[m][3]);
            }
        }
        __syncthreads();
    }

    // ---- Epilogue: + bd, float2 STG ----
    #pragma unroll
    for (int m = 0; m < 8; ++m) {
        int row = i0 + ty * 8 + m;
        size_t rb = (size_t)row * VOCAB;
        #pragma unroll
        for (int p = 0; p < 4; ++p) {
            int cc = n0 + tx * 8 + 2 * p;
            if (cc < VOCAB) {                  // cc even, VOCAB even -> cc+1 ok
                float2 v;
                v.x = lof2(acc[m][p]) + bd[cc];
                v.y = hif2(acc[m][p]) + bd[cc + 1];
                *reinterpret_cast<float2*>(&out[rb + cc]) = v;
            }
        }
    }
}

// ---------------------------------------------------------------------------
// kernel_launch: mx gather -> clustered scan -> f32x2 SIMT projection
// Inputs (metadata order): tokens, h0, kernel, rkernel, bias, Wd, bd
// ---------------------------------------------------------------------------
extern "C" void kernel_launch(void* const* d_in, const int* in_sizes, int n_in,
                              void* d_out, int out_size) {
    const int*   tokens = (const int*)  d_in[0];
    const float* h0     = (const float*)d_in[1];
    const float* Wk     = (const float*)d_in[2];
    const float* rker   = (const float*)d_in[3];
    const float* bias   = (const float*)d_in[4];
    const float* Wd     = (const float*)d_in[5];
    const float* bd     = (const float*)d_in[6];
    float* out = (float*)d_out;

    const long hl_need = (long)VOCAB * T_STEPS * BATCH + (long)BATCH * HID;
    int write_hl = ((long)out_size >= hl_need) ? 1 : 0;

    // 1) embed gather
    mx_kernel<<<(T_STEPS * BATCH * G3) / 256, 256>>>(tokens, Wk, bias);
    // 2) scan: 16 clusters x 8 CTAs x 256 threads
    scan_kernel<<<128, 256>>>(h0, rker, bias, out, write_hl);
    // 3) projection: 40 x 128 tiles of 128x128, f32x2 FFMA
    proj_kernel<<<dim3(NBLK, 128), 256>>>(Wd, bd, out);
}

// round 16
// speedup vs baseline: 1.0298x; 1.0298x over previous
#include <cuda_runtime.h>
#include <cstdint>
#include <math.h>

#define T_STEPS 256
#define BATCH   64
#define HID     256
#define G3      768           // 3*HID
#define VOCAB   5000
#define NBLK    40            // ceil(5000/128)

typedef unsigned long long u64;

// Scratch (static __device__ arrays: allowed; no runtime allocation)
__device__ __align__(16) float    g_MX[(size_t)T_STEPS * BATCH * G3];   // [t][b][3H]
__device__ __align__(16) float    g_Y [(size_t)T_STEPS * BATCH * HID];  // [t][b][H]
__device__ __align__(16) uint32_t g_Yt[(size_t)128 * 8 * 4096];         // A frags (tf32)
__device__ __align__(16) uint32_t g_Wt[(size_t)NBLK * 8 * 4096];        // B frags (tf32)

// ---------------------------------------------------------------------------
// Kernel 1: MX[t][b][n] = kernel[tokens[b][t]][n] + b_in[n]   (gather)
// ---------------------------------------------------------------------------
__global__ void mx_kernel(const int* __restrict__ tokens,
                          const float* __restrict__ Wk,
                          const float* __restrict__ bias) {
    int idx = blockIdx.x * 256 + threadIdx.x;
    int n  = idx % G3;
    int tb = idx / G3;
    int b  = tb % BATCH;
    int t  = tb / BATCH;
    int tok = tokens[b * T_STEPS + t];
    g_MX[idx] = Wk[(size_t)tok * G3 + n] + bias[n];
}

// ---------------------------------------------------------------------------
// Common helpers
// ---------------------------------------------------------------------------
__device__ __forceinline__ uint32_t smem_u32(const void* p) {
    uint32_t a;
    asm("{ .reg .u64 t; cvta.to.shared.u64 t, %1; cvt.u32.u64 %0, t; }"
        : "=r"(a) : "l"(p));
    return a;
}
__device__ __forceinline__ void st_cluster_f32(uint32_t laddr, int rank, float v) {
    uint32_t ra;
    asm volatile("mapa.shared::cluster.u32 %0, %1, %2;" : "=r"(ra) : "r"(laddr), "r"(rank));
    asm volatile("st.shared::cluster.f32 [%0], %1;" :: "r"(ra), "f"(v) : "memory");
}
__device__ __forceinline__ void mbar_arrive_remote_rel(uint32_t laddr, int rank) {
    uint32_t ra;
    asm volatile("mapa.shared::cluster.u32 %0, %1, %2;" : "=r"(ra) : "r"(laddr), "r"(rank));
    asm volatile("mbarrier.arrive.release.cluster.shared::cluster.b64 _, [%0];"
                 :: "r"(ra) : "memory");
}
__device__ __forceinline__ void mbar_wait_acq_cluster(uint32_t addr, uint32_t parity) {
    asm volatile(
        "{\n\t.reg .pred P;\n\t"
        "WL_%=:\n\t"
        "mbarrier.try_wait.parity.acquire.cluster.shared::cta.b64 P, [%0], %1;\n\t"
        "@P bra.uni WD_%=;\n\t"
        "bra.uni WL_%=;\n\t"
        "WD_%=:\n\t}"
        :: "r"(addr), "r"(parity) : "memory");
}
__device__ __forceinline__ u64 fma2(u64 a, u64 b, u64 c) {
    u64 d;
    asm("fma.rn.f32x2 %0, %1, %2, %3;" : "=l"(d) : "l"(a), "l"(b), "l"(c));
    return d;
}
__device__ __forceinline__ u64 packf2(float lo, float hi) {
    u64 d;
    asm("mov.b64 %0, {%1, %2};" : "=l"(d) : "f"(lo), "f"(hi));
    return d;
}
__device__ __forceinline__ float sumf2(u64 p) {
    return __uint_as_float((unsigned)p) + __uint_as_float((unsigned)(p >> 32));
}
__device__ __forceinline__ float sigmoidf_(float x) { return 1.0f / (1.0f + __expf(-x)); }
__device__ __forceinline__ uint32_t f2tf(float f) {
    uint32_t u;
    asm("cvt.rna.tf32.f32 %0, %1;" : "=r"(u) : "f"(f));
    return u;
}

// ---------------------------------------------------------------------------
// Kernel 2: GRU scan — mbarrier producer/consumer sync; ONE cluster barrier
// at start (init visibility) and ONE at end (exit safety: no CTA may exit
// while peers' remote stores/arrives targeting its SMEM are in flight —
// this was the R15 fault). No per-step barrier.cluster => no per-step
// CCTL.IVALL L1 flush, no per-step 8-CTA convergence.
// ---------------------------------------------------------------------------
#define HPAD 288

__global__ void __cluster_dims__(8, 1, 1) __launch_bounds__(256, 1) scan_kernel(
    const float* __restrict__ h0,
    const float* __restrict__ rkernel,
    const float* __restrict__ bias,
    float* __restrict__ out, int write_hlast)
{
    __shared__ float hb[2][4][HPAD];
    __shared__ __align__(8) u64 smbar[4];   // full0, full1, empty0, empty1
    const int tid = threadIdx.x;
    const int jj = tid >> 3;
    const int o  = tid & 7;
    uint32_t crank;
    asm("mov.u32 %0, %%cluster_ctarank;" : "=r"(crank));
    const int cid  = blockIdx.x >> 3;
    const int seq0 = cid * 4;
    const int c    = (int)crank * 32 + jj;
    const int kbase = o * 32;

    u64 w2[3][16];
    #pragma unroll
    for (int g = 0; g < 3; ++g)
        #pragma unroll
        for (int ii = 0; ii < 16; ++ii) {
            float a = rkernel[(size_t)(kbase + 2 * ii)     * G3 + g * HID + c];
            float b = rkernel[(size_t)(kbase + 2 * ii + 1) * G3 + g * HID + c];
            w2[g][ii] = packf2(a, b);
        }
    const float brz = bias[G3 + c];
    const float brr = bias[G3 + HID + c];
    const float brh = bias[G3 + 2 * HID + c];

    for (int e = tid; e < 4 * HID; e += 256) {
        int s = e >> 8, k = e & 255;
        hb[0][s][k + ((k >> 5) << 2)] = h0[(size_t)(seq0 + s) * HID + k];
    }
    const uint32_t hb_base = smem_u32(&hb[0][0][0]);
    const int padc = (int)crank * 36 + jj;

    uint32_t mb_full[2], mb_empty[2];
    mb_full[0]  = smem_u32(&smbar[0]);
    mb_full[1]  = smem_u32(&smbar[1]);
    mb_empty[0] = smem_u32(&smbar[2]);
    mb_empty[1] = smem_u32(&smbar[3]);
    if (tid == 0) {
        asm volatile("mbarrier.init.shared.b64 [%0], %1;" :: "r"(mb_full[0]),  "r"(256u) : "memory");
        asm volatile("mbarrier.init.shared.b64 [%0], %1;" :: "r"(mb_full[1]),  "r"(256u) : "memory");
        asm volatile("mbarrier.init.shared.b64 [%0], %1;" :: "r"(mb_empty[0]), "r"(8u)   : "memory");
        asm volatile("mbarrier.init.shared.b64 [%0], %1;" :: "r"(mb_empty[1]), "r"(8u)   : "memory");
    }
    __syncthreads();
    // one-time cluster sync: all barriers + h0 buffers visible before traffic
    asm volatile("barrier.cluster.arrive.aligned;" ::: "memory");
    asm volatile("barrier.cluster.wait.aligned;"   ::: "memory");

    uint32_t phf[2] = {0u, 0u};   // full-wait phases
    uint32_t phe[2] = {0u, 0u};   // empty-wait phases

    for (int t = 0; t < T_STEPS; ++t) {
        const int cur = t & 1, nxt = cur ^ 1;

        // Issue MX loads first; latency hidden under the full-wait below.
        const float* mxp = g_MX + ((size_t)t * BATCH + seq0) * G3 + c;
        float mxz[4], mxr[4], mxh[4];
        #pragma unroll
        for (int s = 0; s < 4; ++s) {
            mxz[s] = mxp[(size_t)s * G3];
            mxr[s] = mxp[(size_t)s * G3 + HID];
            mxh[s] = mxp[(size_t)s * G3 + 2 * HID];
        }

        if (t > 0) {                      // hb[cur] written by step t-1
            mbar_wait_acq_cluster(mb_full[cur], phf[cur]);
            phf[cur] ^= 1u;
        }

        u64 acc[3][4];
        #pragma unroll
        for (int g = 0; g < 3; ++g)
            #pragma unroll
            for (int s = 0; s < 4; ++s) acc[g][s] = 0ull;
        #pragma unroll
        for (int s = 0; s < 4; ++s) {
            const float* hrow = &hb[cur][s][o * 36];
            #pragma unroll
            for (int q = 0; q < 8; ++q) {
                ulonglong2 hp = *reinterpret_cast<const ulonglong2*>(hrow + q * 4);
                #pragma unroll
                for (int g = 0; g < 3; ++g) {
                    acc[g][s] = fma2(w2[g][2 * q],     hp.x, acc[g][s]);
                    acc[g][s] = fma2(w2[g][2 * q + 1], hp.y, acc[g][s]);
                }
            }
        }
        float red[12];
        #pragma unroll
        for (int g = 0; g < 3; ++g)
            #pragma unroll
            for (int s = 0; s < 4; ++s) red[g * 4 + s] = sumf2(acc[g][s]);
        #pragma unroll
        for (int m = 1; m <= 4; m <<= 1)
            #pragma unroll
            for (int v = 0; v < 12; ++v)
                red[v] += __shfl_xor_sync(0xFFFFFFFFu, red[v], m);

        float hn[4];
        #pragma unroll
        for (int s = 0; s < 4; ++s) {
            float az = red[s], ar = red[4 + s], ah = red[8 + s];
            float z = sigmoidf_(mxz[s] + az + brz);
            float r = sigmoidf_(mxr[s] + ar + brr);
            float cand = tanhf(mxh[s] + r * (ah + brh));
            float hp0 = hb[cur][s][padc];
            hn[s] = z * hp0 + (1.0f - z) * cand;
        }

        __syncthreads();                  // all reads of hb[cur] complete
        if (tid < 8)                      // tell every rank: my hb[cur] is free
            mbar_arrive_remote_rel(mb_empty[cur], tid);

        if (t > 0) {                      // hb[nxt] must be done being read
            mbar_wait_acq_cluster(mb_empty[nxt], phe[nxt]);
            phe[nxt] ^= 1u;
        }

        // Store my col to rank o's next buffer, then release-arrive its full.
        #pragma unroll
        for (int s = 0; s < 4; ++s) {
            uint32_t la = hb_base + (uint32_t)(((nxt * 4 + s) * HPAD + padc) * 4);
            st_cluster_f32(la, o, hn[s]);
        }
        mbar_arrive_remote_rel(mb_full[nxt], o);

        if (o == 0) {
            #pragma unroll
            for (int s = 0; s < 4; ++s)
                g_Y[((size_t)t * BATCH + seq0 + s) * HID + c] = hn[s];
            if (write_hlast && t == T_STEPS - 1) {
                size_t hl = (size_t)VOCAB * (T_STEPS * BATCH);
                #pragma unroll
                for (int s = 0; s < 4; ++s)
                    out[hl + (size_t)(seq0 + s) * HID + c] = hn[s];
            }
        }
    }

    // EXIT SAFETY (the R15 fault): keep all CTAs alive until every peer's
    // remote stores / mbarrier-arrives targeting this CTA's SMEM have landed.
    asm volatile("barrier.cluster.arrive.aligned;" ::: "memory");
    asm volatile("barrier.cluster.wait.aligned;"   ::: "memory");
}

// ---------------------------------------------------------------------------
// Prep A: g_Y -> g_Yt tf32 fragment order (UNCHANGED from passing R13).
// ---------------------------------------------------------------------------
__global__ void __launch_bounds__(256) prepY_kernel() {
    int u = blockIdx.x * 256 + threadIdx.x;     // 0 .. 128*8*1024-1
    int lane = u & 31;
    int frag = (u >> 5) & 31;
    int tile = u >> 10;
    int ch   = tile & 7;
    int mblk = tile >> 3;
    int r = mblk * 128 + (frag >> 2) * 16 + (lane >> 2);
    int k = ch * 32 + (frag & 3) * 8 + (lane & 3);
    const float* yr0 = &g_Y[(size_t)r * HID + k];
    uint4 w;
    w.x = f2tf(yr0[0]);
    w.y = f2tf(yr0[8 * HID]);
    w.z = f2tf(yr0[4]);
    w.w = f2tf(yr0[8 * HID + 4]);
    reinterpret_cast<uint4*>(g_Yt)[u] = w;
}

// ---------------------------------------------------------------------------
// Prep B: Wd -> g_Wt tf32 fragment order (UNCHANGED from passing R13).
// ---------------------------------------------------------------------------
__global__ void __launch_bounds__(256) prepW_kernel(const float* __restrict__ Wd) {
    int v = blockIdx.x * 256 + threadIdx.x;     // 0 .. NBLK*8*2048-1
    int lane = v & 31;
    int frag = (v >> 5) & 63;
    int tile = v >> 11;
    int ch   = tile & 7;
    int nblk = tile >> 3;
    int col = nblk * 128 + (frag >> 2) * 8 + (lane >> 2);
    int k   = ch * 32 + (frag & 3) * 8 + (lane & 3);
    uint2 w = make_uint2(0u, 0u);
    if (col < VOCAB) {
        w.x = f2tf(Wd[(size_t)k * VOCAB + col]);
        w.y = f2tf(Wd[(size_t)(k + 4) * VOCAB + col]);
    }
    reinterpret_cast<uint2*>(g_Wt)[v] = w;
}

// ---------------------------------------------------------------------------
// Kernel 3: register-direct tf32 mma.sync projection (UNCHANGED from R13).
// ---------------------------------------------------------------------------
__device__ __forceinline__ void mma_tf32(float d[4], const uint32_t a[4], const uint32_t b[2]) {
    asm volatile(
        "mma.sync.aligned.m16n8k8.row.col.f32.tf32.tf32.f32 "
        "{%0,%1,%2,%3}, {%4,%5,%6,%7}, {%8,%9}, {%0,%1,%2,%3};\n"
        : "+f"(d[0]), "+f"(d[1]), "+f"(d[2]), "+f"(d[3])
        : "r"(a[0]), "r"(a[1]), "r"(a[2]), "r"(a[3]), "r"(b[0]), "r"(b[1]));
}

__global__ void __launch_bounds__(256) proj_kernel(
    const float* __restrict__ bd, float* __restrict__ out)
{
    const int tid  = threadIdx.x;
    const int lane = tid & 31, wid = tid >> 5;
    const int wr = wid >> 2, wc = wid & 3;
    const int nblk = blockIdx.x;
    const int mblk = blockIdx.y;
    const int n0 = nblk * 128;
    const int i0 = mblk * 128;

    const uint4* baseA = reinterpret_cast<const uint4*>(g_Yt)
                       + (size_t)mblk * 8192 + wr * 512 + lane;
    const uint2* baseB = reinterpret_cast<const uint2*>(g_Wt)
                       + (size_t)nblk * 16384 + wc * 512 + lane;

    float acc[4][4][4];
    #pragma unroll
    for (int mi = 0; mi < 4; mi++)
        #pragma unroll
        for (int ni = 0; ni < 4; ni++)
            #pragma unroll
            for (int q = 0; q < 4; q++) acc[mi][ni][q] = 0.0f;

    uint4 a0[4], a1[4];
    uint2 b0[4], b1[4];

    {
        const uint4* pa = baseA;
        const uint2* pb = baseB;
        #pragma unroll
        for (int mi = 0; mi < 4; mi++) a0[mi] = pa[mi * 128];
        #pragma unroll
        for (int ni = 0; ni < 4; ni++) b0[ni] = pb[ni * 128];
    }

    #pragma unroll
    for (int s = 0; s < 32; s += 2) {
        {
            int t1 = s + 1;
            int ch = t1 >> 2, kk = t1 & 3;
            const uint4* pa = baseA + ch * 1024 + kk * 32;
            const uint2* pb = baseB + ch * 2048 + kk * 32;
            #pragma unroll
            for (int mi = 0; mi < 4; mi++) a1[mi] = pa[mi * 128];
            #pragma unroll
            for (int ni = 0; ni < 4; ni++) b1[ni] = pb[ni * 128];
        }
        #pragma unroll
        for (int mi = 0; mi < 4; mi++)
            #pragma unroll
            for (int ni = 0; ni < 4; ni++)
                mma_tf32(acc[mi][ni],
                         reinterpret_cast<const uint32_t*>(&a0[mi]),
                         reinterpret_cast<const uint32_t*>(&b0[ni]));
        if (s + 2 < 32) {
            int t2 = s + 2;
            int ch = t2 >> 2, kk = t2 & 3;
            const uint4* pa = baseA + ch * 1024 + kk * 32;
            const uint2* pb = baseB + ch * 2048 + kk * 32;
            #pragma unroll
            for (int mi = 0; mi < 4; mi++) a0[mi] = pa[mi * 128];
            #pragma unroll
            for (int ni = 0; ni < 4; ni++) b0[ni] = pb[ni * 128];
        }
        #pragma unroll
        for (int mi = 0; mi < 4; mi++)
            #pragma unroll
            for (int ni = 0; ni < 4; ni++)
                mma_tf32(acc[mi][ni],
                         reinterpret_cast<const uint32_t*>(&a1[mi]),
                         reinterpret_cast<const uint32_t*>(&b1[ni]));
    }

    #pragma unroll
    for (int mi = 0; mi < 4; mi++) {
        int r0 = i0 + wr * 64 + mi * 16 + (lane >> 2);
        #pragma unroll
        for (int ni = 0; ni < 4; ni++) {
            int cbn = n0 + wc * 32 + ni * 8 + ((lane & 3) << 1);
            if (cbn < VOCAB) {
                float b0v = bd[cbn], b1v = bd[cbn + 1];
                out[(size_t)r0 * VOCAB + cbn]           = acc[mi][ni][0] + b0v;
                out[(size_t)r0 * VOCAB + cbn + 1]       = acc[mi][ni][1] + b1v;
                out[(size_t)(r0 + 8) * VOCAB + cbn]     = acc[mi][ni][2] + b0v;
                out[(size_t)(r0 + 8) * VOCAB + cbn + 1] = acc[mi][ni][3] + b1v;
            }
        }
    }
}

// ---------------------------------------------------------------------------
// kernel_launch: mx -> prepW -> scan(mbarrier) -> prepY -> proj
// Inputs (metadata order): tokens, h0, kernel, rkernel, bias, Wd, bd
// ---------------------------------------------------------------------------
extern "C" void kernel_launch(void* const* d_in, const int* in_sizes, int n_in,
                              void* d_out, int out_size) {
    const int*   tokens = (const int*)  d_in[0];
    const float* h0     = (const float*)d_in[1];
    const float* Wk     = (const float*)d_in[2];
    const float* rker   = (const float*)d_in[3];
    const float* bias   = (const float*)d_in[4];
    const float* Wd     = (const float*)d_in[5];
    const float* bd     = (const float*)d_in[6];
    float* out = (float*)d_out;

    const long hl_need = (long)VOCAB * T_STEPS * BATCH + (long)BATCH * HID;
    int write_hl = ((long)out_size >= hl_need) ? 1 : 0;

    // 1) embed gather
    mx_kernel<<<(T_STEPS * BATCH * G3) / 256, 256>>>(tokens, Wk, bias);
    // 2) Wd -> tf32 fragments (independent of scan)
    prepW_kernel<<<(NBLK * 8 * 2048) / 256, 256>>>(Wd);
    // 3) scan: 16 clusters x 8 CTAs x 256 threads, mbarrier sync
    scan_kernel<<<128, 256>>>(h0, rker, bias, out, write_hl);
    // 4) Y -> tf32 fragments
    prepY_kernel<<<(128 * 8 * 1024) / 256, 256>>>();
    // 5) projection: register-direct fragments
    proj_kernel<<<dim3(NBLK, 128), 256>>>(bd, out);
}

// round 17
// speedup vs baseline: 1.5418x; 1.4972x over previous
#include <cuda_runtime.h>
#include <cstdint>
#include <math.h>

#define T_STEPS 256
#define BATCH   64
#define HID     256
#define G3      768           // 3*HID
#define VOCAB   5000
#define NBLK    40            // ceil(5000/128)

typedef unsigned long long u64;

// Scratch (static __device__ arrays: allowed; no runtime allocation)
__device__ __align__(16) float    g_MX[(size_t)T_STEPS * BATCH * G3];   // [t][b][3H]
__device__ __align__(16) float    g_Y [(size_t)T_STEPS * BATCH * HID];  // [t][b][H]
__device__ __align__(16) uint32_t g_Yt[(size_t)128 * 16 * 8 * 32 * 4];  // A frags fp16, 8MB
__device__ __align__(16) uint32_t g_Wt[(size_t)NBLK * 16 * 16 * 32 * 2];// B frags fp16, 2.6MB

// ---------------------------------------------------------------------------
// Kernel 1: MX[t][b][n] = kernel[tokens[b][t]][n] + b_in[n]   (gather)
// ---------------------------------------------------------------------------
__global__ void mx_kernel(const int* __restrict__ tokens,
                          const float* __restrict__ Wk,
                          const float* __restrict__ bias) {
    int idx = blockIdx.x * 256 + threadIdx.x;
    int n  = idx % G3;
    int tb = idx / G3;
    int b  = tb % BATCH;
    int t  = tb / BATCH;
    int tok = tokens[b * T_STEPS + t];
    g_MX[idx] = Wk[(size_t)tok * G3 + n] + bias[n];
}

// ---------------------------------------------------------------------------
// Common helpers
// ---------------------------------------------------------------------------
__device__ __forceinline__ uint32_t smem_u32(const void* p) {
    uint32_t a;
    asm("{ .reg .u64 t; cvta.to.shared.u64 t, %1; cvt.u32.u64 %0, t; }"
        : "=r"(a) : "l"(p));
    return a;
}
__device__ __forceinline__ void st_cluster_f32(uint32_t laddr, int rank, float v) {
    uint32_t ra;
    asm volatile("mapa.shared::cluster.u32 %0, %1, %2;" : "=r"(ra) : "r"(laddr), "r"(rank));
    asm volatile("st.shared::cluster.f32 [%0], %1;" :: "r"(ra), "f"(v) : "memory");
}
__device__ __forceinline__ u64 fma2(u64 a, u64 b, u64 c) {
    u64 d;
    asm("fma.rn.f32x2 %0, %1, %2, %3;" : "=l"(d) : "l"(a), "l"(b), "l"(c));
    return d;
}
__device__ __forceinline__ u64 packf2(float lo, float hi) {
    u64 d;
    asm("mov.b64 %0, {%1, %2};" : "=l"(d) : "f"(lo), "f"(hi));
    return d;
}
__device__ __forceinline__ float sumf2(u64 p) {
    return __uint_as_float((unsigned)p) + __uint_as_float((unsigned)(p >> 32));
}
__device__ __forceinline__ float sigmoidf_(float x) { return 1.0f / (1.0f + __expf(-x)); }
__device__ __forceinline__ uint32_t packh2(float lo, float hi) {
    uint32_t r;
    asm("{ .reg .f16 a, b; cvt.rn.f16.f32 a, %1; cvt.rn.f16.f32 b, %2;"
        "  mov.b32 %0, {a, b}; }" : "=r"(r) : "f"(lo), "f"(hi));
    return r;
}

// ---------------------------------------------------------------------------
// Kernel 2: GRU scan (UNCHANGED from the 1518us R13 build: cluster barrier)
// ---------------------------------------------------------------------------
#define HPAD 288

__global__ void __cluster_dims__(8, 1, 1) __launch_bounds__(256, 1) scan_kernel(
    const float* __restrict__ h0,
    const float* __restrict__ rkernel,
    const float* __restrict__ bias,
    float* __restrict__ out, int write_hlast)
{
    __shared__ float hb[2][4][HPAD];
    const int tid = threadIdx.x;
    const int jj = tid >> 3;
    const int o  = tid & 7;
    uint32_t crank;
    asm("mov.u32 %0, %%cluster_ctarank;" : "=r"(crank));
    const int cid  = blockIdx.x >> 3;
    const int seq0 = cid * 4;
    const int c    = (int)crank * 32 + jj;
    const int kbase = o * 32;

    u64 w2[3][16];
    #pragma unroll
    for (int g = 0; g < 3; ++g)
        #pragma unroll
        for (int ii = 0; ii < 16; ++ii) {
            float a = rkernel[(size_t)(kbase + 2 * ii)     * G3 + g * HID + c];
            float b = rkernel[(size_t)(kbase + 2 * ii + 1) * G3 + g * HID + c];
            w2[g][ii] = packf2(a, b);
        }
    const float brz = bias[G3 + c];
    const float brr = bias[G3 + HID + c];
    const float brh = bias[G3 + 2 * HID + c];

    for (int e = tid; e < 4 * HID; e += 256) {
        int s = e >> 8, k = e & 255;
        hb[0][s][k + ((k >> 5) << 2)] = h0[(size_t)(seq0 + s) * HID + k];
    }
    const uint32_t hb_base = smem_u32(&hb[0][0][0]);
    const int padc = (int)crank * 36 + jj;
    __syncthreads();
    asm volatile("barrier.cluster.arrive.aligned;" ::: "memory");
    asm volatile("barrier.cluster.wait.aligned;"   ::: "memory");

    for (int t = 0; t < T_STEPS; ++t) {
        const int cur = t & 1, nxt = cur ^ 1;
        const float* mxp = g_MX + ((size_t)t * BATCH + seq0) * G3 + c;
        float mxz[4], mxr[4], mxh[4];
        #pragma unroll
        for (int s = 0; s < 4; ++s) {
            mxz[s] = mxp[(size_t)s * G3];
            mxr[s] = mxp[(size_t)s * G3 + HID];
            mxh[s] = mxp[(size_t)s * G3 + 2 * HID];
        }
        u64 acc[3][4];
        #pragma unroll
        for (int g = 0; g < 3; ++g)
            #pragma unroll
            for (int s = 0; s < 4; ++s) acc[g][s] = 0ull;
        #pragma unroll
        for (int s = 0; s < 4; ++s) {
            const float* hrow = &hb[cur][s][o * 36];
            #pragma unroll
            for (int q = 0; q < 8; ++q) {
                ulonglong2 hp = *reinterpret_cast<const ulonglong2*>(hrow + q * 4);
                #pragma unroll
                for (int g = 0; g < 3; ++g) {
                    acc[g][s] = fma2(w2[g][2 * q],     hp.x, acc[g][s]);
                    acc[g][s] = fma2(w2[g][2 * q + 1], hp.y, acc[g][s]);
                }
            }
        }
        float red[12];
        #pragma unroll
        for (int g = 0; g < 3; ++g)
            #pragma unroll
            for (int s = 0; s < 4; ++s) red[g * 4 + s] = sumf2(acc[g][s]);
        #pragma unroll
        for (int m = 1; m <= 4; m <<= 1)
            #pragma unroll
            for (int v = 0; v < 12; ++v)
                red[v] += __shfl_xor_sync(0xFFFFFFFFu, red[v], m);

        float hn[4];
        #pragma unroll
        for (int s = 0; s < 4; ++s) {
            float az = red[s], ar = red[4 + s], ah = red[8 + s];
            float z = sigmoidf_(mxz[s] + az + brz);
            float r = sigmoidf_(mxr[s] + ar + brr);
            float cand = tanhf(mxh[s] + r * (ah + brh));
            float hp0 = hb[cur][s][padc];
            hn[s] = z * hp0 + (1.0f - z) * cand;
        }
        #pragma unroll
        for (int s = 0; s < 4; ++s) {
            uint32_t la = hb_base + (uint32_t)(((nxt * 4 + s) * HPAD + padc) * 4);
            st_cluster_f32(la, o, hn[s]);
        }
        asm volatile("barrier.cluster.arrive.aligned;" ::: "memory");
        if (o == 0) {
            #pragma unroll
            for (int s = 0; s < 4; ++s)
                g_Y[((size_t)t * BATCH + seq0 + s) * HID + c] = hn[s];
            if (write_hlast && t == T_STEPS - 1) {
                size_t hl = (size_t)VOCAB * (T_STEPS * BATCH);
                #pragma unroll
                for (int s = 0; s < 4; ++s)
                    out[hl + (size_t)(seq0 + s) * HID + c] = hn[s];
            }
        }
        asm volatile("barrier.cluster.wait.aligned;" ::: "memory");
    }
}

// ---------------------------------------------------------------------------
// Prep A: g_Y -> g_Yt fp16 fragments for mma.m16n8k16 (A: 4 x b32 = 8 fp16).
// uint4 id u: lane=u&31, frag=(u>>5)&7 (=wr*4+mi), tile=u>>8 (= mblk*16+ch)
//   g=lane>>2, th=lane&3; rowbase = mblk*128 + (frag>>2)*64 + (frag&3)*16 + g
//   ka = ch*16 + th*2; kb = ka + 8
//   words = { h2(Y[r][ka],Y[r][ka+1]), h2(Y[r+8][ka],..), h2(Y[r][kb],..),
//             h2(Y[r+8][kb],..) }
// ---------------------------------------------------------------------------
__global__ void __launch_bounds__(256) prepY_kernel() {
    int u = blockIdx.x * 256 + threadIdx.x;      // 0 .. 128*16*8*32-1 (524288)
    int lane = u & 31;
    int frag = (u >> 5) & 7;
    int tile = u >> 8;
    int ch   = tile & 15;
    int mblk = tile >> 4;
    int g  = lane >> 2, th = lane & 3;
    int r0 = mblk * 128 + (frag >> 2) * 64 + (frag & 3) * 16 + g;
    int ka = ch * 16 + th * 2;
    const float* y0 = &g_Y[(size_t)r0 * HID];
    const float* y1 = y0 + 8 * HID;
    float2 va0 = *reinterpret_cast<const float2*>(y0 + ka);
    float2 va1 = *reinterpret_cast<const float2*>(y1 + ka);
    float2 vb0 = *reinterpret_cast<const float2*>(y0 + ka + 8);
    float2 vb1 = *reinterpret_cast<const float2*>(y1 + ka + 8);
    uint4 w;
    w.x = packh2(va0.x, va0.y);
    w.y = packh2(va1.x, va1.y);
    w.z = packh2(vb0.x, vb0.y);
    w.w = packh2(vb1.x, vb1.y);
    reinterpret_cast<uint4*>(g_Yt)[u] = w;
}

// ---------------------------------------------------------------------------
// Prep B: Wd -> g_Wt fp16 fragments (B: 2 x b32 = 4 fp16), zero-pad past VOCAB.
// uint2 id v: lane=v&31, frag=(v>>5)&15 (=wc*4+ni), tile=v>>9 (= nblk*16+ch)
//   col = nblk*128 + (frag>>2)*32 + (frag&3)*8 + g;  ka = ch*16+th*2; kb=ka+8
//   words = { h2(Wd[ka][col],Wd[ka+1][col]), h2(Wd[kb][col],Wd[kb+1][col]) }
// ---------------------------------------------------------------------------
__global__ void __launch_bounds__(256) prepW_kernel(const float* __restrict__ Wd) {
    int v = blockIdx.x * 256 + threadIdx.x;      // 0 .. NBLK*16*16*32-1 (327680)
    int lane = v & 31;
    int frag = (v >> 5) & 15;
    int tile = v >> 9;
    int ch   = tile & 15;
    int nblk = tile >> 4;
    int g  = lane >> 2, th = lane & 3;
    int col = nblk * 128 + (frag >> 2) * 32 + (frag & 3) * 8 + g;
    int ka  = ch * 16 + th * 2;
    uint2 w = make_uint2(0u, 0u);
    if (col < VOCAB) {
        w.x = packh2(Wd[(size_t)ka * VOCAB + col],       Wd[(size_t)(ka + 1) * VOCAB + col]);
        w.y = packh2(Wd[(size_t)(ka + 8) * VOCAB + col], Wd[(size_t)(ka + 9) * VOCAB + col]);
    }
    reinterpret_cast<uint2*>(g_Wt)[v] = w;
}

// ---------------------------------------------------------------------------
// Kernel 3: out = Y @ Wd + bd, fp16 mma.sync m16n8k16 (fp32 accum),
// register-direct fragment loads (no smem/sync/cvt in mainloop),
// double-buffered over 16 k-steps. 128x128 tile, 8 warps (2x4), warp 64x32.
// ---------------------------------------------------------------------------
__device__ __forceinline__ void mma_f16(float d[4], const uint32_t a[4], const uint32_t b[2]) {
    asm volatile(
        "mma.sync.aligned.m16n8k16.row.col.f32.f16.f16.f32 "
        "{%0,%1,%2,%3}, {%4,%5,%6,%7}, {%8,%9}, {%0,%1,%2,%3};\n"
        : "+f"(d[0]), "+f"(d[1]), "+f"(d[2]), "+f"(d[3])
        : "r"(a[0]), "r"(a[1]), "r"(a[2]), "r"(a[3]), "r"(b[0]), "r"(b[1]));
}

__global__ void __launch_bounds__(256) proj_kernel(
    const float* __restrict__ bd, float* __restrict__ out)
{
    const int tid  = threadIdx.x;
    const int lane = tid & 31, wid = tid >> 5;
    const int wr = wid >> 2, wc = wid & 3;
    const int nblk = blockIdx.x;
    const int mblk = blockIdx.y;
    const int n0 = nblk * 128;
    const int i0 = mblk * 128;

    // A u4 idx = (mblk*16+ch)*8*32 + (wr*4+mi)*32 + lane
    // B u2 idx = (nblk*16+ch)*16*32 + (wc*4+ni)*32 + lane
    const uint4* baseA = reinterpret_cast<const uint4*>(g_Yt)
                       + (size_t)mblk * 4096 + wr * 128 + lane;
    const uint2* baseB = reinterpret_cast<const uint2*>(g_Wt)
                       + (size_t)nblk * 8192 + wc * 128 + lane;

    float acc[4][4][4];
    #pragma unroll
    for (int mi = 0; mi < 4; mi++)
        #pragma unroll
        for (int ni = 0; ni < 4; ni++)
            #pragma unroll
            for (int q = 0; q < 4; q++) acc[mi][ni][q] = 0.0f;

    uint4 a0[4], a1[4];
    uint2 b0[4], b1[4];

    // load k-step 0
    #pragma unroll
    for (int mi = 0; mi < 4; mi++) a0[mi] = baseA[mi * 32];
    #pragma unroll
    for (int ni = 0; ni < 4; ni++) b0[ni] = baseB[ni * 32];

    #pragma unroll
    for (int s = 0; s < 16; s += 2) {
        {   // prefetch step s+1
            const uint4* pa = baseA + (size_t)(s + 1) * 256;
            const uint2* pb = baseB + (size_t)(s + 1) * 512;
            #pragma unroll
            for (int mi = 0; mi < 4; mi++) a1[mi] = pa[mi * 32];
            #pragma unroll
            for (int ni = 0; ni < 4; ni++) b1[ni] = pb[ni * 32];
        }
        #pragma unroll
        for (int mi = 0; mi < 4; mi++)
            #pragma unroll
            for (int ni = 0; ni < 4; ni++)
                mma_f16(acc[mi][ni],
                        reinterpret_cast<const uint32_t*>(&a0[mi]),
                        reinterpret_cast<const uint32_t*>(&b0[ni]));
        if (s + 2 < 16) {   // prefetch step s+2
            const uint4* pa = baseA + (size_t)(s + 2) * 256;
            const uint2* pb = baseB + (size_t)(s + 2) * 512;
            #pragma unroll
            for (int mi = 0; mi < 4; mi++) a0[mi] = pa[mi * 32];
            #pragma unroll
            for (int ni = 0; ni < 4; ni++) b0[ni] = pb[ni * 32];
        }
        #pragma unroll
        for (int mi = 0; mi < 4; mi++)
            #pragma unroll
            for (int ni = 0; ni < 4; ni++)
                mma_f16(acc[mi][ni],
                        reinterpret_cast<const uint32_t*>(&a1[mi]),
                        reinterpret_cast<const uint32_t*>(&b1[ni]));
    }

    // ---- Epilogue (same D layout as k8): + bd, direct STG ----
    #pragma unroll
    for (int mi = 0; mi < 4; mi++) {
        int r0 = i0 + wr * 64 + mi * 16 + (lane >> 2);
        #pragma unroll
        for (int ni = 0; ni < 4; ni++) {
            int cbn = n0 + wc * 32 + ni * 8 + ((lane & 3) << 1);
            if (cbn < VOCAB) {
                float b0v = bd[cbn], b1v = bd[cbn + 1];
                out[(size_t)r0 * VOCAB + cbn]           = acc[mi][ni][0] + b0v;
                out[(size_t)r0 * VOCAB + cbn + 1]       = acc[mi][ni][1] + b1v;
                out[(size_t)(r0 + 8) * VOCAB + cbn]     = acc[mi][ni][2] + b0v;
                out[(size_t)(r0 + 8) * VOCAB + cbn + 1] = acc[mi][ni][3] + b1v;
            }
        }
    }
}

// ---------------------------------------------------------------------------
// kernel_launch: mx -> prepW -> scan(cluster) -> prepY -> proj(fp16 k16)
// Inputs (metadata order): tokens, h0, kernel, rkernel, bias, Wd, bd
// ---------------------------------------------------------------------------
extern "C" void kernel_launch(void* const* d_in, const int* in_sizes, int n_in,
                              void* d_out, int out_size) {
    const int*   tokens = (const int*)  d_in[0];
    const float* h0     = (const float*)d_in[1];
    const float* Wk     = (const float*)d_in[2];
    const float* rker   = (const float*)d_in[3];
    const float* bias   = (const float*)d_in[4];
    const float* Wd     = (const float*)d_in[5];
    const float* bd     = (const float*)d_in[6];
    float* out = (float*)d_out;

    const long hl_need = (long)VOCAB * T_STEPS * BATCH + (long)BATCH * HID;
    int write_hl = ((long)out_size >= hl_need) ? 1 : 0;

    // 1) embed gather
    mx_kernel<<<(T_STEPS * BATCH * G3) / 256, 256>>>(tokens, Wk, bias);
    // 2) Wd -> fp16 fragments (independent of scan): 327680 u2 / 256
    prepW_kernel<<<1280, 256>>>(Wd);
    // 3) scan: 16 clusters x 8 CTAs x 256 threads (cluster barrier)
    scan_kernel<<<128, 256>>>(h0, rker, bias, out, write_hl);
    // 4) Y -> fp16 fragments: 524288 u4 / 256
    prepY_kernel<<<2048, 256>>>();
    // 5) projection: fp16 m16n8k16 register-direct
    proj_kernel<<<dim3(NBLK, 128), 256>>>(bd, out);
}